// round 16
// baseline (speedup 1.0000x reference)
#include <cuda_runtime.h>
#include <cuda_fp16.h>
#include <cstdint>

// Problem constants (fixed by setup_inputs)
#define BB 4
#define CC 128
#define HH 64
#define WW 64
#define OO 128
#define TT 9

// K-order: k = t*128 + c  (tap-major). Chunk ch (64 k): t = ch>>1,
// channels c = (ch&1)*64 .. +63.
// Pre-converted, pre-swizzled fp16 GEMM weights: [18 chunks][16KB]
__device__ __align__(16) char g_wb[18 * 16384];
// Pre-converted, pre-swizzled fp16 conv weights (27 oc padded to 32): [18][4KB]
__device__ __align__(16) char g_wbc[18 * 4096];
// Channel-last transposed input: xt[b][pos(y*64+w)][c]
__device__ __align__(16) float g_xt[BB * 4096 * 128];

// ---------------------------------------------------------------------------
// helpers
// ---------------------------------------------------------------------------
__device__ __forceinline__ uint32_t smem_u32(const void* p) {
    uint32_t a;
    asm("{ .reg .u64 t; cvta.to.shared.u64 t, %1; cvt.u32.u64 %0, t; }"
        : "=r"(a) : "l"(p));
    return a;
}
#define SWZ128(o) ((o) ^ (((o) >> 3) & 0x70))

__device__ __forceinline__ void ldsm_x4(uint32_t* r, uint32_t addr) {
    asm volatile("ldmatrix.sync.aligned.m8n8.x4.shared.b16 {%0,%1,%2,%3}, [%4];"
                 : "=r"(r[0]), "=r"(r[1]), "=r"(r[2]), "=r"(r[3]) : "r"(addr));
}
__device__ __forceinline__ void mma_f16(float* c, const uint32_t* a,
                                        const uint32_t* b) {
    asm volatile("mma.sync.aligned.m16n8k16.row.col.f32.f16.f16.f32 "
                 "{%0,%1,%2,%3}, {%4,%5,%6,%7}, {%8,%9}, {%0,%1,%2,%3};"
                 : "+f"(c[0]), "+f"(c[1]), "+f"(c[2]), "+f"(c[3])
                 : "r"(a[0]), "r"(a[1]), "r"(a[2]), "r"(a[3]),
                   "r"(b[0]), "r"(b[1]));
}
__device__ __forceinline__ uint32_t fp16pack(float v0, float v1) {
    __half2 h = __floats2half2_rn(v0, v1);
    uint32_t r;
    *(__half2*)&r = h;
    return r;
}
__device__ __forceinline__ void cp_async16(uint32_t smem_dst, const void* gsrc) {
    asm volatile("cp.async.cg.shared.global [%0], [%1], 16;"
                 :: "r"(smem_dst), "l"(gsrc) : "memory");
}
__device__ __forceinline__ void cp_commit() {
    asm volatile("cp.async.commit_group;" ::: "memory");
}
__device__ __forceinline__ void cp_wait0() {
    asm volatile("cp.async.wait_group 0;" ::: "memory");
}

// ============================================================================
// Kernel 0: weight prep (new K-order) + x transpose.
//   blocks 0..287   : GEMM weights -> g_wb      (k = t*128+c)
//   blocks 288..359 : conv weights -> g_wbc     (27 oc padded to 32)
//   blocks 360..2407: x[b][c][pos] -> g_xt[b][pos][c]  (32x32 smem tiles)
// ============================================================================
__global__ __launch_bounds__(256) void k0_prep(
    const float* __restrict__ x, const float* __restrict__ wgt,
    const float* __restrict__ ow, const float* __restrict__ mw)
{
    __shared__ float ts[32][33];
    const int blk = blockIdx.x;
    if (blk < 288) {
        int id = blk * 256 + threadIdx.x;  // 73728 items
        int ch = id >> 12;
        int r = id & 4095;
        int o = r >> 5, kp = r & 31;
        int t = ch >> 1;
        int c = ((ch & 1) << 6) + kp * 2;
        float v0 = wgt[o * 1152 + c * 9 + t];
        float v1 = wgt[o * 1152 + (c + 1) * 9 + t];
        uint32_t off = SWZ128((uint32_t)(o * 128 + kp * 4));
        *(uint32_t*)(g_wb + ch * 16384 + off) = fp16pack(v0, v1);
    } else if (blk < 360) {
        int id = (blk - 288) * 256 + threadIdx.x;  // 18432 items
        int ch = id >> 10;
        int r = id & 1023;
        int oc = r >> 5, kp = r & 31;
        int t = ch >> 1;
        int c = ((ch & 1) << 6) + kp * 2;
        float v0 = 0.f, v1 = 0.f;
        if (oc < 18) {
            v0 = ow[oc * 1152 + c * 9 + t];
            v1 = ow[oc * 1152 + (c + 1) * 9 + t];
        } else if (oc < 27) {
            v0 = mw[(oc - 18) * 1152 + c * 9 + t];
            v1 = mw[(oc - 18) * 1152 + (c + 1) * 9 + t];
        }
        uint32_t off = SWZ128((uint32_t)(oc * 128 + kp * 4));
        *(uint32_t*)(g_wbc + ch * 4096 + off) = fp16pack(v0, v1);
    } else {
        const int tb = blk - 360;          // 0..2047
        const int b = tb >> 9;
        const int rem = tb & 511;
        const int ct = rem >> 7;           // 0..3
        const int pt = rem & 127;          // 0..127
        const int c0 = ct * 32, p0 = pt * 32;
        const int row = threadIdx.x >> 5, lane = threadIdx.x & 31;
#pragma unroll
        for (int it = 0; it < 4; it++) {
            int ci = it * 8 + row;
            ts[ci][lane] = x[(b * 128 + c0 + ci) * 4096 + p0 + lane];
        }
        __syncthreads();
#pragma unroll
        for (int it = 0; it < 4; it++) {
            int pi = it * 8 + row;
            g_xt[(size_t)(b * 4096 + p0 + pi) * 128 + c0 + lane] = ts[lane][pi];
        }
    }
}

// ============================================================================
// Fused kernel: per (b,h) row (grid 256, block 256, 2 CTAs/SM):
//   Phase A: 27-ch conv as fp16 implicit GEMM + bias + sigmoid + bilinear
//            metadata -> smem. Thread map per chunk: m = tid&63,
//            16-channel slice cq = (tid>>6)*16; im2col via LDG.128.
//   Phase B: deformable sampling (corner LDG.128 over 4 channels, metadata
//            amortized per chunk) + fp16 GEMM + BN + SiLU + coalesced stores.
// ============================================================================
#define K1STG 12288
#define K1_CONV 24576
#define K2STG 24576
#define SM_WT  49152
#define SM_OFF 58368
#define SM_SC  62976
#define SM_SH  63488
#define SMF_BYTES 64000
#define EP_STRIDE 68

__device__ __forceinline__ void stage_Ac(
    char* buf, const float* __restrict__ xtb, int h, int ch, int tid)
{
    const int t = ch >> 1;
    const int cbase = (ch & 1) << 6;
    const int m = tid & 63;
    const int cq = (tid >> 6) << 4;   // 0,16,32,48
    const int ii = t / 3, jj = t - ii * 3;
    const int y = h + ii - 1;
    const int xw = m + jj - 1;
    const bool valid = ((unsigned)y < 64u) && ((unsigned)xw < 64u);
    const float* src = xtb + (y * 64 + xw) * 128 + cbase + cq;
#pragma unroll
    for (int g = 0; g < 4; g++) {
        float4 q = valid ? *(const float4*)(src + g * 4)
                         : make_float4(0.f, 0.f, 0.f, 0.f);
        uint32_t off = SWZ128((uint32_t)(m * 128 + (cq + g * 4) * 2));
        *(uint2*)(buf + off) = make_uint2(fp16pack(q.x, q.y), fp16pack(q.z, q.w));
    }
}

// Phase B: issue 4 corner LDG.128 (4 channels each) for group g.
__device__ __forceinline__ void issueA(
    float* pf, const float* __restrict__ xtb,
    const ushort4* __restrict__ s_off, int ch, int g, int tid)
{
    const int t = ch >> 1;
    const int m = tid & 63;
    const int c0 = ((ch & 1) << 6) + ((tid >> 6) << 4) + g * 4;
    ushort4 o = s_off[t * 64 + m];
    const float* base = xtb + c0;
    *(float4*)(pf + 0)  = *(const float4*)(base + (int)o.x * 128);
    *(float4*)(pf + 4)  = *(const float4*)(base + (int)o.y * 128);
    *(float4*)(pf + 8)  = *(const float4*)(base + (int)o.z * 128);
    *(float4*)(pf + 12) = *(const float4*)(base + (int)o.w * 128);
}

// Phase B: bilinear combine 4 channels, pack, STS.64 into A tile.
__device__ __forceinline__ void consumeA(
    char* buf, const float* pf,
    const float4* __restrict__ s_wt, int ch, int g, int tid)
{
    const int t = ch >> 1;
    const int m = tid & 63;
    const int klq = ((tid >> 6) << 4) + g * 4;
    float4 w = s_wt[t * 64 + m];
    float s0 = w.x * pf[0] + w.y * pf[4] + w.z * pf[8]  + w.w * pf[12];
    float s1 = w.x * pf[1] + w.y * pf[5] + w.z * pf[9]  + w.w * pf[13];
    float s2 = w.x * pf[2] + w.y * pf[6] + w.z * pf[10] + w.w * pf[14];
    float s3 = w.x * pf[3] + w.y * pf[7] + w.z * pf[11] + w.w * pf[15];
    uint32_t off = SWZ128((uint32_t)(m * 128 + klq * 2));
    *(uint2*)(buf + off) = make_uint2(fp16pack(s0, s1), fp16pack(s2, s3));
}

__global__ __launch_bounds__(256, 2) void k12_fused(
    const float* __restrict__ ob, const float* __restrict__ mb,
    const float* __restrict__ gamma, const float* __restrict__ beta,
    const float* __restrict__ mean, const float* __restrict__ var,
    float* __restrict__ out)
{
    extern __shared__ char sm[];
    const uint32_t sb = smem_u32(sm);
    const int tid = threadIdx.x;
    const int wid = tid >> 5, lid = tid & 31;
    const int bh = blockIdx.x;
    const int b = bh >> 6;
    const int h = bh & 63;
    const float* xtb = g_xt + (size_t)b * 524288;

    float4* s_wt = (float4*)(sm + SM_WT);
    ushort4* s_off = (ushort4*)(sm + SM_OFF);
    float* s_sc = (float*)(sm + SM_SC);
    float* s_sh = (float*)(sm + SM_SH);

    if (tid < 128) {
        float sc = gamma[tid] * rsqrtf(var[tid] + 1e-5f);
        s_sc[tid] = sc;
        s_sh[tid] = beta[tid] - mean[tid] * sc;
    }

    // ============================ Phase A: conv + meta ============================
    {
        const int wM = (wid & 3) * 16;
        const int wN = (wid >> 2) * 16;
        const int a_row = lid & 15;
        const int a_col = (lid >> 4) * 8;
        const int b_row = (lid & 7) + ((lid >> 4) << 3);
        const int b_col = ((lid >> 3) & 1) * 8;

        float acc[2][4];
#pragma unroll
        for (int nt = 0; nt < 2; nt++)
#pragma unroll
            for (int i = 0; i < 4; i++) acc[nt][i] = 0.f;

        // prologue
        cp_async16(sb + 8192 + tid * 16, g_wbc + tid * 16);
        cp_commit();
        stage_Ac(sm, xtb, h, 0, tid);
        cp_wait0();
        __syncthreads();

        for (int ch = 0; ch < 18; ch++) {
            const int cur = ch & 1;
            const uint32_t baseA = sb + cur * K1STG;
            char* nxt = sm + (cur ^ 1) * K1STG;

            if (ch < 17) {
                cp_async16(sb + (cur ^ 1) * K1STG + 8192 + tid * 16,
                           g_wbc + (ch + 1) * 4096 + tid * 16);
                cp_commit();
            }

#pragma unroll
            for (int ks = 0; ks < 4; ks++) {
                uint32_t bhf[4];
                {
                    uint32_t off = SWZ128((uint32_t)((wN + b_row) * 128 +
                                                     (ks * 16 + b_col) * 2));
                    ldsm_x4(bhf, baseA + 8192 + off);
                }
                uint32_t ah[4];
                uint32_t off = SWZ128((uint32_t)((wM + a_row) * 128 +
                                                 (ks * 16 + a_col) * 2));
                ldsm_x4(ah, baseA + off);
#pragma unroll
                for (int nt = 0; nt < 2; nt++)
                    mma_f16(acc[nt], ah, &bhf[nt * 2]);
            }

            if (ch < 17) stage_Ac(nxt, xtb, h, ch + 1, tid);
            cp_wait0();
            __syncthreads();
        }

        // conv sums -> smem
        float* cbuf = (float*)(sm + K1_CONV);
        const int g = lid >> 2, t2 = (lid & 3) * 2;
#pragma unroll
        for (int nt = 0; nt < 2; nt++) {
#pragma unroll
            for (int i = 0; i < 4; i++) {
                int n = wN + nt * 8 + t2 + (i & 1);
                if (n >= 27) continue;
                int m = wM + g + ((i >> 1) ? 8 : 0);
                cbuf[n * 64 + m] = acc[nt][i];
            }
        }
        __syncthreads();

        // meta epilogue -> smem s_wt / s_off
        for (int i = tid; i < TT * 64; i += 256) {
            int t = i >> 6, ww = i & 63;
            float s0 = cbuf[(2 * t) * 64 + ww];
            float s1 = cbuf[(2 * t + 1) * 64 + ww];
            float s2 = cbuf[(18 + t) * 64 + ww];
            float offy = s0 + ob[2 * t];
            float offx = s1 + ob[2 * t + 1];
            float m = 1.f / (1.f + __expf(-(s2 + mb[t])));

            int ii = t / 3;
            int jj = t - ii * 3;
            float py = (float)(h - 1 + ii) + offy;
            float px = (float)(ww - 1 + jj) + offx;
            float fy = floorf(py), fx = floorf(px);
            float ly = py - fy, lx = px - fx;
            int y0 = (int)fy, x0 = (int)fx;
            float hy = 1.f - ly, hx = 1.f - lx;
            float w00 = hy * hx * m, w01 = hy * lx * m;
            float w10 = ly * hx * m, w11 = ly * lx * m;
            bool vy0 = (unsigned)y0 < 64u;
            bool vy1 = (unsigned)(y0 + 1) < 64u;
            bool vx0 = (unsigned)x0 < 64u;
            bool vx1 = (unsigned)(x0 + 1) < 64u;
            if (!(vy0 && vx0)) w00 = 0.f;
            if (!(vy0 && vx1)) w01 = 0.f;
            if (!(vy1 && vx0)) w10 = 0.f;
            if (!(vy1 && vx1)) w11 = 0.f;
            int y0a = min(max(y0, 0), 63), y1a = min(max(y0 + 1, 0), 63);
            int x0a = min(max(x0, 0), 63), x1a = min(max(x0 + 1, 0), 63);
            s_wt[i] = make_float4(w00, w01, w10, w11);
            s_off[i] = make_ushort4((unsigned short)(y0a * 64 + x0a),
                                    (unsigned short)(y0a * 64 + x1a),
                                    (unsigned short)(y1a * 64 + x0a),
                                    (unsigned short)(y1a * 64 + x1a));
        }
    }
    __syncthreads();

    // ======================= Phase B: deformable GEMM =======================
    {
        const int wM = (wid & 1) * 32;
        const int wN = (wid >> 1) * 32;
        const int a_row = lid & 15;
        const int a_col = (lid >> 4) * 8;
        const int b_row = (lid & 7) + ((lid >> 4) << 3);
        const int b_col = ((lid >> 3) & 1) * 8;

        float acc[2][4][4];
#pragma unroll
        for (int mt = 0; mt < 2; mt++)
#pragma unroll
            for (int nt = 0; nt < 4; nt++)
#pragma unroll
                for (int i = 0; i < 4; i++) acc[mt][nt][i] = 0.f;

        float pf[16];

        // prologue: stage chunk 0 into buf 0
        {
            uint32_t bsm = sb + 8192;
#pragma unroll
            for (int it = 0; it < 4; it++) {
                int ln = it * 256 + tid;
                cp_async16(bsm + ln * 16, g_wb + ln * 16);
            }
            cp_commit();
#pragma unroll
            for (int g = 0; g < 4; g++) {
                issueA(pf, xtb, s_off, 0, g, tid);
                consumeA(sm, pf, s_wt, 0, g, tid);
            }
            cp_wait0();
        }
        __syncthreads();

        for (int ch = 0; ch < 18; ch++) {
            const int cur = ch & 1;
            const uint32_t baseA = sb + cur * K2STG;
            char* nxt = sm + (cur ^ 1) * K2STG;
            const bool more = (ch < 17);

            if (more) {
                uint32_t bsm = sb + (cur ^ 1) * K2STG + 8192;
                const char* gsrc = g_wb + (ch + 1) * 16384;
#pragma unroll
                for (int it = 0; it < 4; it++) {
                    int ln = it * 256 + tid;
                    cp_async16(bsm + ln * 16, gsrc + ln * 16);
                }
                cp_commit();
                issueA(pf, xtb, s_off, ch + 1, 0, tid);
            }

#pragma unroll
            for (int ks = 0; ks < 4; ks++) {
                uint32_t ah[2][4];
#pragma unroll
                for (int mt = 0; mt < 2; mt++) {
                    uint32_t off = SWZ128((uint32_t)((wM + mt * 16 + a_row) * 128 +
                                                     (ks * 16 + a_col) * 2));
                    ldsm_x4(ah[mt], baseA + off);
                }
                uint32_t bhf[2][4];
#pragma unroll
                for (int p = 0; p < 2; p++) {
                    uint32_t off = SWZ128((uint32_t)((wN + p * 16 + b_row) * 128 +
                                                     (ks * 16 + b_col) * 2));
                    ldsm_x4(bhf[p], baseA + 8192 + off);
                }
#pragma unroll
                for (int mt = 0; mt < 2; mt++)
#pragma unroll
                    for (int nt = 0; nt < 4; nt++)
                        mma_f16(acc[mt][nt], ah[mt], &bhf[nt >> 1][(nt & 1) * 2]);

                if (more) {
                    consumeA(nxt, pf, s_wt, ch + 1, ks, tid);
                    if (ks < 3) issueA(pf, xtb, s_off, ch + 1, ks + 1, tid);
                }
            }

            cp_wait0();
            __syncthreads();
        }

        // epilogue: BN + SiLU -> smem tile -> coalesced stores
        float* obuf = (float*)sm;
        const int g = lid >> 2, t2 = (lid & 3) * 2;
#pragma unroll
        for (int mt = 0; mt < 2; mt++) {
#pragma unroll
            for (int nt = 0; nt < 4; nt++) {
#pragma unroll
                for (int i = 0; i < 4; i++) {
                    int m = wM + mt * 16 + g + ((i >> 1) ? 8 : 0);
                    int n = wN + nt * 8 + t2 + (i & 1);
                    float v = acc[mt][nt][i] * s_sc[n] + s_sh[n];
                    v = v / (1.f + __expf(-v));
                    obuf[n * EP_STRIDE + m] = v;
                }
            }
        }
        __syncthreads();
        for (int i = tid; i < 2048; i += 256) {
            int n = i >> 4;
            int mq = (i & 15) * 4;
            float4 v4 = *(const float4*)(obuf + n * EP_STRIDE + mq);
            *(float4*)(out + ((b * OO + n) * HH + h) * WW + mq) = v4;
        }
    }
}

extern "C" void kernel_launch(void* const* d_in, const int* in_sizes, int n_in,
                              void* d_out, int out_size)
{
    const float* x  = (const float*)d_in[0];
    const float* ow = (const float*)d_in[1];
    const float* ob = (const float*)d_in[2];
    const float* mw = (const float*)d_in[3];
    const float* mb = (const float*)d_in[4];
    const float* wg = (const float*)d_in[5];
    const float* gg = (const float*)d_in[6];
    const float* bt = (const float*)d_in[7];
    const float* mu = (const float*)d_in[8];
    const float* vr = (const float*)d_in[9];
    float* out = (float*)d_out;

    cudaFuncSetAttribute(k12_fused,
                         cudaFuncAttributeMaxDynamicSharedMemorySize, SMF_BYTES);

    k0_prep<<<2408, 256>>>(x, wg, ow, mw);
    k12_fused<<<BB * HH, 256, SMF_BYTES>>>(ob, mb, gg, bt, mu, vr, out);
}

// round 17
// speedup vs baseline: 1.8990x; 1.8990x over previous
#include <cuda_runtime.h>
#include <cuda_fp16.h>
#include <cstdint>

// Problem constants (fixed by setup_inputs)
#define BB 4
#define CC 128
#define HH 64
#define WW 64
#define OO 128
#define TT 9

// K-order: k = t*128 + c (tap-major). Chunk ch: t = ch>>1, c = (ch&1)*64 ..+63.
// Pre-converted, pre-swizzled fp16 GEMM weights: [18 chunks][16KB]
__device__ __align__(16) char g_wb[18 * 16384];
// Pre-converted, pre-swizzled fp16 conv weights (27 oc padded to 32): [18][4KB]
__device__ __align__(16) char g_wbc[18 * 4096];

// ---------------------------------------------------------------------------
// helpers
// ---------------------------------------------------------------------------
__device__ __forceinline__ uint32_t smem_u32(const void* p) {
    uint32_t a;
    asm("{ .reg .u64 t; cvta.to.shared.u64 t, %1; cvt.u32.u64 %0, t; }"
        : "=r"(a) : "l"(p));
    return a;
}
#define SWZ128(o) ((o) ^ (((o) >> 3) & 0x70))

__device__ __forceinline__ void ldsm_x4(uint32_t* r, uint32_t addr) {
    asm volatile("ldmatrix.sync.aligned.m8n8.x4.shared.b16 {%0,%1,%2,%3}, [%4];"
                 : "=r"(r[0]), "=r"(r[1]), "=r"(r[2]), "=r"(r[3]) : "r"(addr));
}
__device__ __forceinline__ void mma_f16(float* c, const uint32_t* a,
                                        const uint32_t* b) {
    asm volatile("mma.sync.aligned.m16n8k16.row.col.f32.f16.f16.f32 "
                 "{%0,%1,%2,%3}, {%4,%5,%6,%7}, {%8,%9}, {%0,%1,%2,%3};"
                 : "+f"(c[0]), "+f"(c[1]), "+f"(c[2]), "+f"(c[3])
                 : "r"(a[0]), "r"(a[1]), "r"(a[2]), "r"(a[3]),
                   "r"(b[0]), "r"(b[1]));
}
__device__ __forceinline__ uint32_t fp16pack(float v0, float v1) {
    __half2 h = __floats2half2_rn(v0, v1);
    uint32_t r;
    *(__half2*)&r = h;
    return r;
}
__device__ __forceinline__ void cp_async16(uint32_t smem_dst, const void* gsrc) {
    asm volatile("cp.async.cg.shared.global [%0], [%1], 16;"
                 :: "r"(smem_dst), "l"(gsrc) : "memory");
}
__device__ __forceinline__ void cp_commit() {
    asm volatile("cp.async.commit_group;" ::: "memory");
}
__device__ __forceinline__ void cp_wait0() {
    asm volatile("cp.async.wait_group 0;" ::: "memory");
}

// ============================================================================
// Kernel 0: weight prep, t-major K order.
//   blocks 0..287   : GEMM weights -> g_wb
//   blocks 288..359 : conv weights -> g_wbc (27 oc padded to 32)
// ============================================================================
__global__ __launch_bounds__(256) void k0_prep(
    const float* __restrict__ wgt,
    const float* __restrict__ ow, const float* __restrict__ mw)
{
    const int blk = blockIdx.x;
    if (blk < 288) {
        int id = blk * 256 + threadIdx.x;  // 73728 items
        int ch = id >> 12;
        int r = id & 4095;
        int o = r >> 5, kp = r & 31;
        int t = ch >> 1;
        int c = ((ch & 1) << 6) + kp * 2;
        float v0 = wgt[o * 1152 + c * 9 + t];
        float v1 = wgt[o * 1152 + (c + 1) * 9 + t];
        uint32_t off = SWZ128((uint32_t)(o * 128 + kp * 4));
        *(uint32_t*)(g_wb + ch * 16384 + off) = fp16pack(v0, v1);
    } else {
        int id = (blk - 288) * 256 + threadIdx.x;  // 18432 items
        int ch = id >> 10;
        int r = id & 1023;
        int oc = r >> 5, kp = r & 31;
        int t = ch >> 1;
        int c = ((ch & 1) << 6) + kp * 2;
        float v0 = 0.f, v1 = 0.f;
        if (oc < 18) {
            v0 = ow[oc * 1152 + c * 9 + t];
            v1 = ow[oc * 1152 + (c + 1) * 9 + t];
        } else if (oc < 27) {
            v0 = mw[(oc - 18) * 1152 + c * 9 + t];
            v1 = mw[(oc - 18) * 1152 + (c + 1) * 9 + t];
        }
        uint32_t off = SWZ128((uint32_t)(oc * 128 + kp * 4));
        *(uint32_t*)(g_wbc + ch * 4096 + off) = fp16pack(v0, v1);
    }
}

// ============================================================================
// Fused kernel: per (b,h) row (grid 256, block 256, 2 CTAs/SM).
// t-major chunks: per chunk one tap -> metadata chunk-invariant per thread.
// Gathers stay position-major coherent: lanes = 32 consecutive pixels of one
// channel. Phase A conv + meta -> smem; Phase B deform GEMM + BN + SiLU.
// ============================================================================
#define K1STG 12288
#define K1_CONV 24576
#define K2STG 24576
#define SM_WT  49152
#define SM_OFF 58368
#define SM_SC  62976
#define SM_SH  63488
#define SMF_BYTES 64000
#define EP_STRIDE 68

// Phase A im2col staging: one tap per chunk, per thread 2 m x 8 c samples.
__device__ __forceinline__ void stage_Ac(
    char* buf, const float* __restrict__ xb, int h, int ch, int wid, int lane)
{
    const int t = ch >> 1;
    const int cbase = (ch & 1) << 6;
    const int ii = t / 3, jj = t - ii * 3;
    const int y = h + ii - 1;
    const bool vy = (unsigned)y < 64u;
#pragma unroll
    for (int msel = 0; msel < 2; msel++) {
        const int m = lane + msel * 32;
        const int xw = m + jj - 1;
        const bool valid = vy && ((unsigned)xw < 64u);
        const int pos = y * 64 + xw;
#pragma unroll
        for (int csp = 0; csp < 4; csp++) {
            const int kloc = wid * 8 + csp * 2;
            const float* xp = xb + (cbase + kloc) * 4096;
            float v0 = valid ? xp[pos] : 0.f;
            float v1 = valid ? xp[4096 + pos] : 0.f;
            uint32_t off = SWZ128((uint32_t)(m * 128 + kloc * 2));
            *(uint32_t*)(buf + off) = fp16pack(v0, v1);
        }
    }
}

// Phase B: issue 16 corner LDG.32 for group g (2 channels x 2 m x 4 corners).
__device__ __forceinline__ void issueB(
    float* pf, const float* __restrict__ xb, int cbase, int g, int wid,
    ushort4 o0, ushort4 o1)
{
    const float* xp0 = xb + (cbase + wid * 8 + g * 2) * 4096;
    const float* xp1 = xp0 + 4096;
    pf[0]  = xp0[o0.x]; pf[1]  = xp0[o0.y]; pf[2]  = xp0[o0.z]; pf[3]  = xp0[o0.w];
    pf[4]  = xp0[o1.x]; pf[5]  = xp0[o1.y]; pf[6]  = xp0[o1.z]; pf[7]  = xp0[o1.w];
    pf[8]  = xp1[o0.x]; pf[9]  = xp1[o0.y]; pf[10] = xp1[o0.z]; pf[11] = xp1[o0.w];
    pf[12] = xp1[o1.x]; pf[13] = xp1[o1.y]; pf[14] = xp1[o1.z]; pf[15] = xp1[o1.w];
}

// Phase B: bilinear combine + pack adjacent-k pairs + 2 STS.32.
__device__ __forceinline__ void consumeB(
    char* buf, const float* pf, int g, int wid, int lane,
    float4 w0, float4 w1)
{
    const int kloc = wid * 8 + g * 2;
    float a0 = w0.x * pf[0]  + w0.y * pf[1]  + w0.z * pf[2]  + w0.w * pf[3];
    float b0 = w1.x * pf[4]  + w1.y * pf[5]  + w1.z * pf[6]  + w1.w * pf[7];
    float a1 = w0.x * pf[8]  + w0.y * pf[9]  + w0.z * pf[10] + w0.w * pf[11];
    float b1 = w1.x * pf[12] + w1.y * pf[13] + w1.z * pf[14] + w1.w * pf[15];
    uint32_t offA = SWZ128((uint32_t)(lane * 128 + kloc * 2));
    *(uint32_t*)(buf + offA) = fp16pack(a0, a1);
    uint32_t offB = SWZ128((uint32_t)((lane + 32) * 128 + kloc * 2));
    *(uint32_t*)(buf + offB) = fp16pack(b0, b1);
}

__global__ __launch_bounds__(256, 2) void k12_fused(
    const float* __restrict__ x,
    const float* __restrict__ ob, const float* __restrict__ mb,
    const float* __restrict__ gamma, const float* __restrict__ beta,
    const float* __restrict__ mean, const float* __restrict__ var,
    float* __restrict__ out)
{
    extern __shared__ char sm[];
    const uint32_t sb = smem_u32(sm);
    const int tid = threadIdx.x;
    const int wid = tid >> 5, lid = tid & 31;
    const int bh = blockIdx.x;
    const int b = bh >> 6;
    const int h = bh & 63;
    const float* xb = x + b * CC * HH * WW;

    float4* s_wt = (float4*)(sm + SM_WT);
    ushort4* s_off = (ushort4*)(sm + SM_OFF);
    float* s_sc = (float*)(sm + SM_SC);
    float* s_sh = (float*)(sm + SM_SH);

    if (tid < 128) {
        float sc = gamma[tid] * rsqrtf(var[tid] + 1e-5f);
        s_sc[tid] = sc;
        s_sh[tid] = beta[tid] - mean[tid] * sc;
    }

    // ============================ Phase A: conv + meta ============================
    {
        const int wM = (wid & 3) * 16;
        const int wN = (wid >> 2) * 16;
        const int a_row = lid & 15;
        const int a_col = (lid >> 4) * 8;
        const int b_row = (lid & 7) + ((lid >> 4) << 3);
        const int b_col = ((lid >> 3) & 1) * 8;

        float acc[2][4];
#pragma unroll
        for (int nt = 0; nt < 2; nt++)
#pragma unroll
            for (int i = 0; i < 4; i++) acc[nt][i] = 0.f;

        // prologue
        cp_async16(sb + 8192 + tid * 16, g_wbc + tid * 16);
        cp_commit();
        stage_Ac(sm, xb, h, 0, wid, lid);
        cp_wait0();
        __syncthreads();

        for (int ch = 0; ch < 18; ch++) {
            const int cur = ch & 1;
            const uint32_t baseA = sb + cur * K1STG;
            char* nxt = sm + (cur ^ 1) * K1STG;

            if (ch < 17) {
                cp_async16(sb + (cur ^ 1) * K1STG + 8192 + tid * 16,
                           g_wbc + (ch + 1) * 4096 + tid * 16);
                cp_commit();
            }

#pragma unroll
            for (int ks = 0; ks < 4; ks++) {
                uint32_t bhf[4];
                {
                    uint32_t off = SWZ128((uint32_t)((wN + b_row) * 128 +
                                                     (ks * 16 + b_col) * 2));
                    ldsm_x4(bhf, baseA + 8192 + off);
                }
                uint32_t ah[4];
                uint32_t off = SWZ128((uint32_t)((wM + a_row) * 128 +
                                                 (ks * 16 + a_col) * 2));
                ldsm_x4(ah, baseA + off);
#pragma unroll
                for (int nt = 0; nt < 2; nt++)
                    mma_f16(acc[nt], ah, &bhf[nt * 2]);
            }

            if (ch < 17) stage_Ac(nxt, xb, h, ch + 1, wid, lid);
            cp_wait0();
            __syncthreads();
        }

        // conv sums -> smem
        float* cbuf = (float*)(sm + K1_CONV);
        const int g = lid >> 2, t2 = (lid & 3) * 2;
#pragma unroll
        for (int nt = 0; nt < 2; nt++) {
#pragma unroll
            for (int i = 0; i < 4; i++) {
                int n = wN + nt * 8 + t2 + (i & 1);
                if (n >= 27) continue;
                int m = wM + g + ((i >> 1) ? 8 : 0);
                cbuf[n * 64 + m] = acc[nt][i];
            }
        }
        __syncthreads();

        // meta epilogue -> smem s_wt / s_off
        for (int i = tid; i < TT * 64; i += 256) {
            int t = i >> 6, ww = i & 63;
            float s0 = cbuf[(2 * t) * 64 + ww];
            float s1 = cbuf[(2 * t + 1) * 64 + ww];
            float s2 = cbuf[(18 + t) * 64 + ww];
            float offy = s0 + ob[2 * t];
            float offx = s1 + ob[2 * t + 1];
            float m = 1.f / (1.f + __expf(-(s2 + mb[t])));

            int ii = t / 3;
            int jj = t - ii * 3;
            float py = (float)(h - 1 + ii) + offy;
            float px = (float)(ww - 1 + jj) + offx;
            float fy = floorf(py), fx = floorf(px);
            float ly = py - fy, lx = px - fx;
            int y0 = (int)fy, x0 = (int)fx;
            float hy = 1.f - ly, hx = 1.f - lx;
            float w00 = hy * hx * m, w01 = hy * lx * m;
            float w10 = ly * hx * m, w11 = ly * lx * m;
            bool vy0 = (unsigned)y0 < 64u;
            bool vy1 = (unsigned)(y0 + 1) < 64u;
            bool vx0 = (unsigned)x0 < 64u;
            bool vx1 = (unsigned)(x0 + 1) < 64u;
            if (!(vy0 && vx0)) w00 = 0.f;
            if (!(vy0 && vx1)) w01 = 0.f;
            if (!(vy1 && vx0)) w10 = 0.f;
            if (!(vy1 && vx1)) w11 = 0.f;
            int y0a = min(max(y0, 0), 63), y1a = min(max(y0 + 1, 0), 63);
            int x0a = min(max(x0, 0), 63), x1a = min(max(x0 + 1, 0), 63);
            s_wt[i] = make_float4(w00, w01, w10, w11);
            s_off[i] = make_ushort4((unsigned short)(y0a * 64 + x0a),
                                    (unsigned short)(y0a * 64 + x1a),
                                    (unsigned short)(y1a * 64 + x0a),
                                    (unsigned short)(y1a * 64 + x1a));
        }
    }
    __syncthreads();

    // ======================= Phase B: deformable GEMM =======================
    {
        const int wM = (wid & 1) * 32;
        const int wN = (wid >> 1) * 32;
        const int a_row = lid & 15;
        const int a_col = (lid >> 4) * 8;
        const int b_row = (lid & 7) + ((lid >> 4) << 3);
        const int b_col = ((lid >> 3) & 1) * 8;

        float acc[2][4][4];
#pragma unroll
        for (int mt = 0; mt < 2; mt++)
#pragma unroll
            for (int nt = 0; nt < 4; nt++)
#pragma unroll
                for (int i = 0; i < 4; i++) acc[mt][nt][i] = 0.f;

        float pf[16];
        ushort4 o0, o1;
        float4 w0, w1;

        // prologue: stage chunk 0 into buf 0
        {
            uint32_t bsm = sb + 8192;
#pragma unroll
            for (int it = 0; it < 4; it++) {
                int ln = it * 256 + tid;
                cp_async16(bsm + ln * 16, g_wb + ln * 16);
            }
            cp_commit();
            o0 = s_off[lid];
            o1 = s_off[32 + lid];
            w0 = s_wt[lid];
            w1 = s_wt[32 + lid];
#pragma unroll
            for (int g = 0; g < 4; g++) {
                issueB(pf, xb, 0, g, wid, o0, o1);
                consumeB(sm, pf, g, wid, lid, w0, w1);
            }
            cp_wait0();
        }
        __syncthreads();

        for (int ch = 0; ch < 18; ch++) {
            const int cur = ch & 1;
            const uint32_t baseA = sb + cur * K2STG;
            char* nxt = sm + (cur ^ 1) * K2STG;
            const bool more = (ch < 17);
            const int tn = (ch + 1) >> 1;
            const int cbn = ((ch + 1) & 1) << 6;

            if (more) {
                uint32_t bsm = sb + (cur ^ 1) * K2STG + 8192;
                const char* gsrc = g_wb + (ch + 1) * 16384;
#pragma unroll
                for (int it = 0; it < 4; it++) {
                    int ln = it * 256 + tid;
                    cp_async16(bsm + ln * 16, gsrc + ln * 16);
                }
                cp_commit();
                o0 = s_off[tn * 64 + lid];
                o1 = s_off[tn * 64 + 32 + lid];
                w0 = s_wt[tn * 64 + lid];
                w1 = s_wt[tn * 64 + 32 + lid];
                issueB(pf, xb, cbn, 0, wid, o0, o1);
            }

#pragma unroll
            for (int ks = 0; ks < 4; ks++) {
                uint32_t ah[2][4];
#pragma unroll
                for (int mt = 0; mt < 2; mt++) {
                    uint32_t off = SWZ128((uint32_t)((wM + mt * 16 + a_row) * 128 +
                                                     (ks * 16 + a_col) * 2));
                    ldsm_x4(ah[mt], baseA + off);
                }
                uint32_t bhf[2][4];
#pragma unroll
                for (int p = 0; p < 2; p++) {
                    uint32_t off = SWZ128((uint32_t)((wN + p * 16 + b_row) * 128 +
                                                     (ks * 16 + b_col) * 2));
                    ldsm_x4(bhf[p], baseA + 8192 + off);
                }
#pragma unroll
                for (int mt = 0; mt < 2; mt++)
#pragma unroll
                    for (int nt = 0; nt < 4; nt++)
                        mma_f16(acc[mt][nt], ah[mt], &bhf[nt >> 1][(nt & 1) * 2]);

                if (more) {
                    consumeB(nxt, pf, ks, wid, lid, w0, w1);
                    if (ks < 3) issueB(pf, xb, cbn, ks + 1, wid, o0, o1);
                }
            }

            cp_wait0();
            __syncthreads();
        }

        // epilogue: BN + SiLU -> smem tile -> coalesced stores
        float* obuf = (float*)sm;
        const int g = lid >> 2, t2 = (lid & 3) * 2;
#pragma unroll
        for (int mt = 0; mt < 2; mt++) {
#pragma unroll
            for (int nt = 0; nt < 4; nt++) {
#pragma unroll
                for (int i = 0; i < 4; i++) {
                    int m = wM + mt * 16 + g + ((i >> 1) ? 8 : 0);
                    int n = wN + nt * 8 + t2 + (i & 1);
                    float v = acc[mt][nt][i] * s_sc[n] + s_sh[n];
                    v = v / (1.f + __expf(-v));
                    obuf[n * EP_STRIDE + m] = v;
                }
            }
        }
        __syncthreads();
        for (int i = tid; i < 2048; i += 256) {
            int n = i >> 4;
            int mq = (i & 15) * 4;
            float4 v4 = *(const float4*)(obuf + n * EP_STRIDE + mq);
            *(float4*)(out + ((b * OO + n) * HH + h) * WW + mq) = v4;
        }
    }
}

extern "C" void kernel_launch(void* const* d_in, const int* in_sizes, int n_in,
                              void* d_out, int out_size)
{
    const float* x  = (const float*)d_in[0];
    const float* ow = (const float*)d_in[1];
    const float* ob = (const float*)d_in[2];
    const float* mw = (const float*)d_in[3];
    const float* mb = (const float*)d_in[4];
    const float* wg = (const float*)d_in[5];
    const float* gg = (const float*)d_in[6];
    const float* bt = (const float*)d_in[7];
    const float* mu = (const float*)d_in[8];
    const float* vr = (const float*)d_in[9];
    float* out = (float*)d_out;

    cudaFuncSetAttribute(k12_fused,
                         cudaFuncAttributeMaxDynamicSharedMemorySize, SMF_BYTES);

    k0_prep<<<360, 256>>>(wg, ow, mw);
    k12_fused<<<BB * HH, 256, SMF_BYTES>>>(x, ob, mb, gg, bt, mu, vr, out);
}